// round 9
// baseline (speedup 1.0000x reference)
#include <cuda_runtime.h>
#include <cuda_bf16.h>

// Problem dims (fixed by the reference)
#define BB 16
#define TT 512     // text tokens
#define AA 4096    // audio frames
#define DD 256     // hidden dim
#define GUARD 64   // numerator truncation radius: exp(-64^2/100) ~ e^-41
#define NSEG 8     // frame-range segments per token in phase B
#define NBLK 256   // grid size (co-resident: 2/SM x 148 = 296 >= 256)

// -(1/TEMP^2) * log2(e):  exp(-d^2/100) == exp2(d^2 * KNEG)
#define KNEG (-0.014426950408889634f)

// Scratch (device globals; every element rewritten each launch -> no zeroing).
__device__ float g_inv[BB * AA];         // per-frame inverse softmax denominator
__device__ float g_Wp[NSEG * BB * TT];   // per-segment token-weight partials
// Monotonic grid-barrier counter (generation style; never reset; deterministic).
__device__ unsigned long long g_ctr = 0ULL;

__device__ __forceinline__ float ex2a(float x) {
    float y; asm("ex2.approx.ftz.f32 %0, %1;" : "=f"(y) : "f"(x)); return y;
}
__device__ __forceinline__ float rcpa(float x) {
    float y; asm("rcp.approx.ftz.f32 %0, %1;" : "=f"(y) : "f"(x)); return y;
}

__device__ __forceinline__ void grid_barrier(int tid) {
    __threadfence();          // publish this block's global writes
    __syncthreads();
    __shared__ unsigned long long tgt;
    if (tid == 0) {
        const unsigned long long old = atomicAdd(&g_ctr, 1ULL);
        tgt = (old / NBLK + 1ULL) * NBLK;
        while (*((volatile unsigned long long*)&g_ctr) < tgt) { }
    }
    __syncthreads();
    __threadfence();          // acquire others' writes
}

// Fused kernel: denom -> barrier -> numer -> barrier -> weighted reduce.
// Grid: 256 blocks x 256 threads.
__global__ __launch_bounds__(256, 2) void aligner_fused(
    const float* __restrict__ hidden,    // [B, D, T]
    const float* __restrict__ centers,   // [B, T] (sorted per b)
    float* __restrict__ out)             // [B, D]
{
    const int tid  = threadIdx.x;
    const int lane = tid & 31;
    const int warp = tid >> 5;
    const int blk  = blockIdx.x;

    // Phase A: centers; Phase C: weight vector (float4-accessed -> align 16).
    __shared__ alignas(16) float sc[TT];

    // ================= Phase A: denominators =================
    // block -> (b, 256-frame chunk); thread-per-frame.
    {
        const int b  = blk >> 4;
        const int ch = blk & 15;
        const int a  = ch * 256 + tid;
        const float ts = (float)a;   // audio_ts[b][a] == a (broadcast arange)

        for (int i = tid; i < TT; i += 256) sc[i] = centers[b * TT + i];
        __syncthreads();

        // first center >= ts
        int lo = 0, hi = TT;
#pragma unroll
        for (int it = 0; it < 9; it++) {  // 2^9 = 512
            const int mid = (lo + hi) >> 1;
            if (sc[mid] < ts) lo = mid + 1; else hi = mid;
        }
        const int j0 = min(max(lo - 32, 0), TT - 64);

        // 64 exps, 4 independent chains
        float s0 = 0.f, s1 = 0.f, s2 = 0.f, s3 = 0.f;
#pragma unroll
        for (int k = 0; k < 64; k += 4) {
            const float d0 = sc[j0 + k + 0] - ts;
            const float d1 = sc[j0 + k + 1] - ts;
            const float d2 = sc[j0 + k + 2] - ts;
            const float d3 = sc[j0 + k + 3] - ts;
            s0 += ex2a(KNEG * d0 * d0);
            s1 += ex2a(KNEG * d1 * d1);
            s2 += ex2a(KNEG * d2 * d2);
            s3 += ex2a(KNEG * d3 * d3);
        }
        g_inv[b * AA + a] = rcpa((s0 + s1) + (s2 + s3));
    }

    grid_barrier(tid);

    // ================= Phase B: numerator scatter =================
    // block -> (b, token-group, segment); thread-per-(token, segment).
    {
        const int b   = blk >> 4;
        const int tg  = (blk >> 3) & 1;
        const int seg = blk & 7;
        const int t   = tg * 256 + tid;

        const float c = __ldg(centers + b * TT + t);
        const int alo = max(0, (int)c - GUARD);
        const int ahi = min(AA, (int)c + GUARD + 1);
        const int len = (ahi - alo + NSEG - 1) / NSEG;
        const int s0  = alo + seg * len;
        const int s1  = min(ahi, s0 + len);

        const float* inv = g_inv + b * AA;

        float acc0 = 0.0f, acc1 = 0.0f;
        int a = s0;
        for (; a + 1 < s1; a += 2) {
            const float d0 = (float)a - c;
            const float d1 = (float)(a + 1) - c;
            acc0 = fmaf(ex2a(KNEG * d0 * d0), __ldg(inv + a), acc0);
            acc1 = fmaf(ex2a(KNEG * d1 * d1), __ldg(inv + a + 1), acc1);
        }
        if (a < s1) {
            const float d = (float)a - c;
            acc0 = fmaf(ex2a(KNEG * d * d), __ldg(inv + a), acc0);
        }
        g_Wp[(seg * BB + b) * TT + t] = acc0 + acc1;
    }

    grid_barrier(tid);

    // ================= Phase C: weighted reduce =================
    // block -> (b, 16-d group); warp computes 2 d's; float4 loads.
    {
        const int b    = blk >> 4;
        const int dblk = blk & 15;

        float4* w4 = (float4*)sc;   // reuse smem (aligned 16 above)
        __syncthreads();
        if (tid < TT / 4) {
            float4 v = make_float4(0.f, 0.f, 0.f, 0.f);
#pragma unroll
            for (int s = 0; s < NSEG; s++) {
                const float4 p = ((const float4*)(g_Wp + (s * BB + b) * TT))[tid];
                v.x += p.x; v.y += p.y; v.z += p.z; v.w += p.w;
            }
            w4[tid] = v;
        }
        __syncthreads();

#pragma unroll
        for (int j = 0; j < 2; j++) {
            const int d = dblk * 16 + warp * 2 + j;
            const float4* h4 = (const float4*)(hidden + ((size_t)(b * DD + d)) * TT);
            float s = 0.0f;
#pragma unroll
            for (int k = 0; k < 4; k++) {
                const int i = lane + 32 * k;
                const float4 h = __ldg(h4 + i);
                const float4 w = w4[i];
                s = fmaf(h.x, w.x, fmaf(h.y, w.y, fmaf(h.z, w.z, fmaf(h.w, w.w, s))));
            }
#pragma unroll
            for (int o = 16; o >= 1; o >>= 1)
                s += __shfl_xor_sync(0xffffffffu, s, o);
            if (lane == 0) out[b * DD + d] = s;
        }
    }
}

extern "C" void kernel_launch(void* const* d_in, const int* in_sizes, int n_in,
                              void* d_out, int out_size) {
    const float* hidden   = (const float*)d_in[0];  // [B, D, T] f32
    const float* centers  = (const float*)d_in[1];  // [B, T]    f32
    float* out = (float*)d_out;                     // [B, D]    f32

    (void)in_sizes; (void)n_in; (void)out_size;

    aligner_fused<<<NBLK, 256>>>(hidden, centers, out);
}

// round 10
// speedup vs baseline: 1.3824x; 1.3824x over previous
#include <cuda_runtime.h>
#include <cuda_bf16.h>

// Problem dims (fixed by the reference)
#define BB 16
#define TT 512     // text tokens
#define AA 4096    // audio frames
#define DD 256     // hidden dim
#define GUARD 64   // numerator truncation radius: exp(-64^2/100) ~ e^-41
#define NSEG 8     // frame-range segments per token in K2
#define WIN 32     // denominator token window (see clustering analysis)

// -(1/TEMP^2) * log2(e):  exp(-d^2/100) == exp2(d^2 * KNEG)
#define KNEG (-0.014426950408889634f)

// Scratch (device globals; every element rewritten each launch -> no zeroing).
__device__ float g_inv[BB * AA];         // per-frame inverse softmax denominator
__device__ float g_Wp[NSEG * BB * TT];   // per-segment token-weight partials

__device__ __forceinline__ float ex2a(float x) {
    float y; asm("ex2.approx.ftz.f32 %0, %1;" : "=f"(y) : "f"(x)); return y;
}
__device__ __forceinline__ float rcpa(float x) {
    float y; asm("rcp.approx.ftz.f32 %0, %1;" : "=f"(y) : "f"(x)); return y;
}

// K1: per-frame softmax denominator over a 32-token window around the
// frame's nearest center. Frame-per-thread; audio_ts[b][a] == a.
// Grid: BB * 32 = 512 blocks x 128 threads (128-frame chunks).
__global__ __launch_bounds__(128) void denom_kernel(
    const float* __restrict__ centers)   // [B, T] (sorted per b)
{
    const int b    = blockIdx.x >> 5;
    const int ch   = blockIdx.x & 31;
    const int tid  = threadIdx.x;
    const int base = ch * 128;
    const float ts = (float)(base + tid);

    __shared__ float sc[TT];
    __shared__ int   anch[17];
    for (int i = tid; i < TT; i += 128) sc[i] = centers[b * TT + i];
    __syncthreads();

    // 17 anchors at 8-frame stride: first center >= base + 8*i
    if (tid < 17) {
        const float tgt = (float)(base + tid * 8);
        int lo = 0, hi = TT;
#pragma unroll
        for (int it = 0; it < 9; it++) {
            const int mid = (lo + hi) >> 1;
            if (sc[mid] < tgt) lo = mid + 1; else hi = mid;
        }
        anch[tid] = lo;
    }
    __syncthreads();

    // Linear advance from anchor (few steps: tokens within 8 timestamps).
    int j = anch[tid >> 3];
    const int jend = anch[(tid >> 3) + 1];
    while (j < jend && sc[j] < ts) j++;
    const int j0 = min(max(j - WIN / 2, 0), TT - WIN);

    // 32 exps, 4 independent chains
    float s0 = 0.f, s1 = 0.f, s2 = 0.f, s3 = 0.f;
#pragma unroll
    for (int k = 0; k < WIN; k += 4) {
        const float d0 = sc[j0 + k + 0] - ts;
        const float d1 = sc[j0 + k + 1] - ts;
        const float d2 = sc[j0 + k + 2] - ts;
        const float d3 = sc[j0 + k + 3] - ts;
        s0 += ex2a((KNEG * d0) * d0);
        s1 += ex2a((KNEG * d1) * d1);
        s2 += ex2a((KNEG * d2) * d2);
        s3 += ex2a((KNEG * d3) * d3);
    }
    g_inv[b * AA + base + tid] = rcpa((s0 + s1) + (s2 + s3));
}

// K2: token-weight numerator scatter. Thread per (token, segment),
// ~2*GUARD/NSEG frames each, register accumulation, dense disjoint writes.
// Grid: BB * 2 * NSEG = 256 blocks x 256 threads.
__global__ __launch_bounds__(256) void numer_kernel(
    const float* __restrict__ centers)   // [B, T]
{
    const int b   = blockIdx.x >> 4;
    const int tg  = (blockIdx.x >> 3) & 1;
    const int seg = blockIdx.x & 7;
    const int t   = tg * 256 + threadIdx.x;

    const float c = __ldg(centers + b * TT + t);
    const int alo = max(0, (int)c - GUARD);
    const int ahi = min(AA, (int)c + GUARD + 1);
    const int len = (ahi - alo + NSEG - 1) / NSEG;
    const int s0  = alo + seg * len;
    const int s1  = min(ahi, s0 + len);

    const float* inv = g_inv + b * AA;

    float acc0 = 0.0f, acc1 = 0.0f;
    int a = s0;
    for (; a + 1 < s1; a += 2) {
        const float d0 = (float)a - c;
        const float d1 = (float)(a + 1) - c;
        acc0 = fmaf(ex2a((KNEG * d0) * d0), __ldg(inv + a), acc0);
        acc1 = fmaf(ex2a((KNEG * d1) * d1), __ldg(inv + a + 1), acc1);
    }
    if (a < s1) {
        const float d = (float)a - c;
        acc0 = fmaf(ex2a((KNEG * d) * d), __ldg(inv + a), acc0);
    }
    g_Wp[(seg * BB + b) * TT + t] = acc0 + acc1;
}

// K3: out[b,d] = sum_t hidden[b,d,t] * W[b,t], W = sum of NSEG partials.
// Grid: 512 blocks x 256 threads; warp-per-row, float4 loads.
__global__ __launch_bounds__(256) void weighted_reduce_kernel(
    const float* __restrict__ hidden,  // [B, D, T]
    float* __restrict__ out)           // [B, D]
{
    const int b    = blockIdx.x >> 5;   // 32 blocks per batch
    const int dblk = blockIdx.x & 31;   // 8 d per block (warp per d)
    const int tid  = threadIdx.x;
    const int lane = tid & 31;
    const int warp = tid >> 5;

    __shared__ float4 w4[TT / 4];
    if (tid < TT / 4) {
        float4 v = make_float4(0.f, 0.f, 0.f, 0.f);
#pragma unroll
        for (int s = 0; s < NSEG; s++) {
            const float4 p = ((const float4*)(g_Wp + (s * BB + b) * TT))[tid];
            v.x += p.x; v.y += p.y; v.z += p.z; v.w += p.w;
        }
        w4[tid] = v;
    }
    __syncthreads();

    const int d = dblk * 8 + warp;
    const float4* h4 = (const float4*)(hidden + ((size_t)(b * DD + d)) * TT);

    float s = 0.0f;
#pragma unroll
    for (int k = 0; k < 4; k++) {
        const int j = lane + 32 * k;
        const float4 h = __ldg(h4 + j);
        const float4 w = w4[j];
        s = fmaf(h.x, w.x, fmaf(h.y, w.y, fmaf(h.z, w.z, fmaf(h.w, w.w, s))));
    }
#pragma unroll
    for (int o = 16; o >= 1; o >>= 1)
        s += __shfl_xor_sync(0xffffffffu, s, o);

    if (lane == 0) out[b * DD + d] = s;
}

extern "C" void kernel_launch(void* const* d_in, const int* in_sizes, int n_in,
                              void* d_out, int out_size) {
    const float* hidden   = (const float*)d_in[0];  // [B, D, T] f32
    const float* centers  = (const float*)d_in[1];  // [B, T]    f32
    float* out = (float*)d_out;                     // [B, D]    f32

    (void)in_sizes; (void)n_in; (void)out_size;

    denom_kernel<<<BB * 32, 128>>>(centers);
    numer_kernel<<<BB * 2 * NSEG, 256>>>(centers);
    weighted_reduce_kernel<<<BB * 32, 256>>>(hidden, out);
}

// round 12
// speedup vs baseline: 1.6930x; 1.2247x over previous
#include <cuda_runtime.h>
#include <cuda_bf16.h>

// Problem dims (fixed by the reference)
#define BB 16
#define TT 512     // text tokens
#define AA 4096    // audio frames
#define DD 256     // hidden dim
#define GUARD 48   // numerator truncation radius: exp(-48^2/100) ~ 1e-10
#define WIN 32     // denominator token window
#define CH 256     // frames per chunk
#define NCH (AA / CH)  // 16 chunks per batch

// -(1/TEMP^2) * log2(e):  exp(-d^2/100) == exp2(d^2 * KNEG)
#define KNEG (-0.014426950408889634f)

// 3-slot token-weight partials (slot = owning chunk relative to token's
// primary chunk). Every element written exactly once per launch.
__device__ float g_Wp[3 * BB * TT];

__device__ __forceinline__ float ex2a(float x) {
    float y; asm("ex2.approx.ftz.f32 %0, %1;" : "=f"(y) : "f"(x)); return y;
}
__device__ __forceinline__ float rcpa(float x) {
    float y; asm("rcp.approx.ftz.f32 %0, %1;" : "=f"(y) : "f"(x)); return y;
}

// M1: fused denominators + numerator scatter, one block per (b, frame chunk).
// Phase A: inv[a] for the 256 owned frames -> smem (thread-per-frame).
// Phase B: for every token whose +/-GUARD window intersects this chunk,
//          accumulate sum_a e(t,a)*inv[a] over owned frames (4 threads/token),
//          write to slot s = C - p(t) + 1 (dense, disjoint, no zeroing).
// Grid: BB * NCH = 256 blocks x 256 threads.
__global__ __launch_bounds__(256) void fused_weights_kernel(
    const float* __restrict__ centers)   // [B, T] (sorted per b)
{
    const int b   = blockIdx.x >> 4;
    const int C   = blockIdx.x & 15;
    const int tid = threadIdx.x;
    const int a0  = C * CH;

    __shared__ float sc[TT];
    __shared__ float sinv[CH];
    __shared__ int   anch[17];
    __shared__ int   tb[4];   // token boundaries of chunks C-1, C, C+1, C+2

    for (int i = tid; i < TT; i += 256) sc[i] = centers[b * TT + i];
    __syncthreads();

    // anchors: first center >= a0 + 16*i  (17 searches, stride-16 frames)
    if (tid < 17) {
        const float tgt = (float)(a0 + tid * 16);
        int lo = 0, hi = TT;
#pragma unroll
        for (int it = 0; it < 9; it++) {
            const int mid = (lo + hi) >> 1;
            if (sc[mid] < tgt) lo = mid + 1; else hi = mid;
        }
        anch[tid] = lo;
    }
    // token-range boundaries: first center >= 256*(C-1+j), j=0..3
    if (tid >= 32 && tid < 36) {
        const float tgt = (float)(CH * (C - 1 + (tid - 32)));
        int lo = 0, hi = TT;
#pragma unroll
        for (int it = 0; it < 9; it++) {
            const int mid = (lo + hi) >> 1;
            if (sc[mid] < tgt) lo = mid + 1; else hi = mid;
        }
        tb[tid - 32] = lo;
    }
    __syncthreads();

    // ---------- Phase A: denominators for owned frames ----------
    {
        const float ts = (float)(a0 + tid);
        int j = anch[tid >> 4];
        const int jend = anch[(tid >> 4) + 1];
        while (j < jend && sc[j] < ts) j++;
        const int j0 = min(max(j - WIN / 2, 0), TT - WIN);

        float s0 = 0.f, s1 = 0.f, s2 = 0.f, s3 = 0.f;
#pragma unroll
        for (int k = 0; k < WIN; k += 4) {
            const float d0 = sc[j0 + k + 0] - ts;
            const float d1 = sc[j0 + k + 1] - ts;
            const float d2 = sc[j0 + k + 2] - ts;
            const float d3 = sc[j0 + k + 3] - ts;
            s0 += ex2a((KNEG * d0) * d0);
            s1 += ex2a((KNEG * d1) * d1);
            s2 += ex2a((KNEG * d2) * d2);
            s3 += ex2a((KNEG * d3) * d3);
        }
        sinv[tid] = rcpa((s0 + s1) + (s2 + s3));
    }
    __syncthreads();

    // ---------- Phase B: numerators over owned frames ----------
    const int t0 = tb[0], t1 = tb[1], t2 = tb[2], t3 = tb[3];
    const int q  = tid & 3;               // quad member: frames lo+q, step 4
    const int NT = t3 - t0;
    const int trips = (NT + 63) >> 6;     // 64 tokens per trip (256 thr / 4)

    for (int k = 0; k < trips; k++) {
        const int i = t0 + (tid >> 2) + (k << 6);
        float acc = 0.0f;
        if (i < t3) {
            const float c = sc[i];
            const int alo = max(0, (int)c - GUARD);
            const int ahi = min(AA, (int)c + GUARD + 1);
            const int lo  = max(alo, a0);
            const int hi  = min(ahi, a0 + CH);
            for (int a = lo + q; a < hi; a += 4) {
                const float d = (float)a - c;
                acc = fmaf(ex2a((KNEG * d) * d), sinv[a - a0], acc);
            }
        }
        acc += __shfl_xor_sync(0xffffffffu, acc, 1);
        acc += __shfl_xor_sync(0xffffffffu, acc, 2);
        if (q == 0 && i < t3) {
            // primary chunk p: [t0,t1)->C-1, [t1,t2)->C, [t2,t3)->C+1
            const int p = (i < t1) ? (C - 1) : ((i < t2) ? C : (C + 1));
            const int s = C - p + 1;                   // 2, 1, 0
            g_Wp[(s * BB + b) * TT + i] = acc;
        }
    }

    // Boundary zero-fill: slot 0 of p=0 tokens (writer C=-1 doesn't exist),
    // slot 2 of p=15 tokens (writer C=16 doesn't exist).
    if (C == 0)
        for (int i = t1 + tid; i < t2; i += 256)
            g_Wp[(0 * BB + b) * TT + i] = 0.0f;
    if (C == NCH - 1)
        for (int i = t1 + tid; i < t2; i += 256)
            g_Wp[(2 * BB + b) * TT + i] = 0.0f;
}

// M2: out[b,d] = sum_t hidden[b,d,t] * W[b,t], W = sum of 3 slots.
// Grid: 512 blocks x 256 threads; warp-per-row, float4 loads.
__global__ __launch_bounds__(256) void weighted_reduce_kernel(
    const float* __restrict__ hidden,  // [B, D, T]
    float* __restrict__ out)           // [B, D]
{
    const int b    = blockIdx.x >> 5;   // 32 blocks per batch
    const int dblk = blockIdx.x & 31;   // 8 d per block (warp per d)
    const int tid  = threadIdx.x;
    const int lane = tid & 31;
    const int warp = tid >> 5;

    __shared__ float4 w4[TT / 4];
    if (tid < TT / 4) {
        float4 v = make_float4(0.f, 0.f, 0.f, 0.f);
#pragma unroll
        for (int s = 0; s < 3; s++) {
            const float4 p = ((const float4*)(g_Wp + (s * BB + b) * TT))[tid];
            v.x += p.x; v.y += p.y; v.z += p.z; v.w += p.w;
        }
        w4[tid] = v;
    }
    __syncthreads();

    const int d = dblk * 8 + warp;
    const float4* h4 = (const float4*)(hidden + ((size_t)(b * DD + d)) * TT);

    float s = 0.0f;
#pragma unroll
    for (int k = 0; k < 4; k++) {
        const int j = lane + 32 * k;
        const float4 h = __ldg(h4 + j);
        const float4 w = w4[j];
        s = fmaf(h.x, w.x, fmaf(h.y, w.y, fmaf(h.z, w.z, fmaf(h.w, w.w, s))));
    }
#pragma unroll
    for (int o = 16; o >= 1; o >>= 1)
        s += __shfl_xor_sync(0xffffffffu, s, o);

    if (lane == 0) out[b * DD + d] = s;
}

extern "C" void kernel_launch(void* const* d_in, const int* in_sizes, int n_in,
                              void* d_out, int out_size) {
    const float* hidden   = (const float*)d_in[0];  // [B, D, T] f32
    const float* centers  = (const float*)d_in[1];  // [B, T]    f32
    float* out = (float*)d_out;                     // [B, D]    f32

    (void)in_sizes; (void)n_in; (void)out_size;

    fused_weights_kernel<<<BB * NCH, 256>>>(centers);
    weighted_reduce_kernel<<<BB * 32, 256>>>(hidden, out);
}